// round 14
// baseline (speedup 1.0000x reference)
#include <cuda_runtime.h>
#include <cuda_bf16.h>

#define TS      36      // smem row stride in floats (34 used + 2 pad; float4-aligned)
#define NPAIRS  4096    // 8192 images = 4096 image pairs
#define GRIDSZ  740     // 5 CTAs/SM x 148 SMs = exactly one resident wave

using ull = unsigned long long;

// ---- packed f32x2 helpers (sm_100+ PTX; ptxas never auto-fuses these) ----
__device__ __forceinline__ ull pack2(float lo, float hi) {
    ull r;
    asm("mov.b64 %0, {%1, %2};" : "=l"(r)
        : "r"(__float_as_uint(lo)), "r"(__float_as_uint(hi)));
    return r;
}
__device__ __forceinline__ void unpack2(ull v, float& lo, float& hi) {
    unsigned a, b;
    asm("mov.b64 {%0, %1}, %2;" : "=r"(a), "=r"(b) : "l"(v));
    lo = __uint_as_float(a); hi = __uint_as_float(b);
}
__device__ __forceinline__ ull ffma2(ull a, ull b, ull c) {
    ull d; asm("fma.rn.f32x2 %0, %1, %2, %3;" : "=l"(d) : "l"(a), "l"(b), "l"(c));
    return d;
}
__device__ __forceinline__ ull fmul2(ull a, ull b) {
    ull d; asm("mul.rn.f32x2 %0, %1, %2;" : "=l"(d) : "l"(a), "l"(b));
    return d;
}
__device__ __forceinline__ ull fadd2(ull a, ull b) {
    ull d; asm("add.rn.f32x2 %0, %1, %2;" : "=l"(d) : "l"(a), "l"(b));
    return d;
}

__global__ __launch_bounds__(256, 5)
void quan2d_kernel(const float4* __restrict__ x4,
                   const float* __restrict__ w,
                   float4* __restrict__ out4)
{
    // Double-buffered pair of 34x34 zero-padded image tiles.
    __shared__ float tile[2][2][34 * TS];
    __shared__ ull grp[8], grn[8];   // packed {r,r}, {-r,-r}, r = tan(theta/2)

    const int tid = threadIdx.x;

    if (tid < 8) {
        float sv, cv;
        sincosf(w[tid] * 0.5f, &sv, &cv);
        float r = __fdividef(sv, cv);   // global cosine factors cancel in <Z> ratio
        grp[tid] = pack2(r, r);
        grn[tid] = pack2(-r, -r);
    }

    // Zero the pad regions of all 4 tiles ONCE. Pads (cols 32..35 rows 0..33,
    // rows 32..33 cols 0..31) are disjoint from the cp.async target region
    // (rows 0..31, cols 0..31), so they stay zero across all iterations.
    if (tid < 200) {
        int tl = tid / 50, u = tid % 50;               // tile 0..3, element 0..49
        float* bp = &tile[tl >> 1][tl & 1][0];
        const float4 z4 = make_float4(0.f, 0.f, 0.f, 0.f);
        if (u < 34) {
            *reinterpret_cast<float4*>(&bp[u * TS + 32]) = z4;
        } else {
            int v = u - 34;                            // 0..15
            *reinterpret_cast<float4*>(&bp[(32 + (v >> 3)) * TS + ((v & 7) << 2)]) = z4;
        }
    }

    const int rr = tid >> 3, c4 = (tid & 7) << 2;      // copy slot: row, col4
    const int ph = tid >> 4, pw = tid & 15;            // patch coords
    const int gbase = (ph * 2) * TS + (pw * 2);

    // Issue async copy of image pair p into buffer buf (1 float4 per image per thread).
    auto issue = [&](int p, int buf) {
        const float4* src = x4 + p * 512 + tid;
        unsigned d0 = (unsigned)__cvta_generic_to_shared(&tile[buf][0][rr * TS + c4]);
        unsigned d1 = (unsigned)__cvta_generic_to_shared(&tile[buf][1][rr * TS + c4]);
        asm volatile("cp.async.cg.shared.global [%0], [%1], 16;" :: "r"(d0), "l"(src));
        asm volatile("cp.async.cg.shared.global [%0], [%1], 16;" :: "r"(d1), "l"(src + 256));
        asm volatile("cp.async.commit_group;");
    };

    int p = blockIdx.x;
    issue(p, 0);                                       // prologue: pair 0 -> buf 0
    int buf = 0;

    for (; p < NPAIRS; p += GRIDSZ, buf ^= 1) {
        asm volatile("cp.async.wait_group 0;" ::: "memory");
        __syncthreads();                               // pair p visible to all; all past prev compute

        int pn = p + GRIDSZ;
        if (pn < NPAIRS) issue(pn, buf ^ 1);           // overlaps this pair's compute

        // Gather: amplitudes packed {img0, img1}; j = dr*4+dc; wire0 = MSB (mask 8)
        ull a[16];
#pragma unroll
        for (int dr = 0; dr < 4; ++dr) {
            const float2* r0p = reinterpret_cast<const float2*>(&tile[buf][0][gbase + dr * TS]);
            const float2* r1p = reinterpret_cast<const float2*>(&tile[buf][1][gbase + dr * TS]);
            float2 p0a = r0p[0], p0b = r0p[1];
            float2 p1a = r1p[0], p1b = r1p[1];
            a[dr * 4 + 0] = pack2(p0a.x, p1a.x);
            a[dr * 4 + 1] = pack2(p0a.y, p1a.y);
            a[dr * 4 + 2] = pack2(p0b.x, p1b.x);
            a[dr * 4 + 3] = pack2(p0b.y, p1b.y);
        }

        // RY (tangent form, cosine deferred): new0 = t0 - r*t1 ; new1 = r*t0 + t1
        auto ry = [&](int m, int gi) {
            ull r2  = grp[gi];
            ull nr2 = grn[gi];
#pragma unroll
            for (int j = 0; j < 16; ++j) {
                if (j & m) continue;
                ull t0 = a[j], t1 = a[j | m];
                a[j]     = ffma2(nr2, t1, t0);
                a[j | m] = ffma2(r2,  t0, t1);
            }
        };
        auto cnot = [&](int cb, int tb) {
#pragma unroll
            for (int j = 0; j < 16; ++j)
                if ((j & cb) && !(j & tb)) { ull t = a[j]; a[j] = a[j | tb]; a[j | tb] = t; }
        };

        ry(8, 0); ry(4, 1); ry(2, 2); ry(1, 3);
        cnot(8, 4); cnot(4, 2); cnot(2, 1); cnot(1, 8);
        ry(8, 4); ry(4, 5); ry(2, 6); ry(1, 7);

        // Group sums of squares:
        //   G[g] = sum a[j]^2, j with (bit3,bit2) = g ; H[g] = same for (bit1,bit0)
        ull G[4], H[4];
#pragma unroll
        for (int g = 0; g < 4; ++g) {
            ull acc = fmul2(a[g * 4], a[g * 4]);
#pragma unroll
            for (int k = 1; k < 4; ++k) acc = ffma2(a[g * 4 + k], a[g * 4 + k], acc);
            G[g] = acc;
            ull acc2 = fmul2(a[g], a[g]);
#pragma unroll
            for (int k = 1; k < 4; ++k) acc2 = ffma2(a[k * 4 + g], a[k * 4 + g], acc2);
            H[g] = acc2;
        }
        ull nrm2 = fadd2(fadd2(G[0], G[1]), fadd2(G[2], G[3]));
        ull s0p = fadd2(G[2], G[3]);   // wire0 (bit3)
        ull s1p = fadd2(G[1], G[3]);   // wire1 (bit2)
        ull s2p = fadd2(H[2], H[3]);   // wire2 (bit1)
        ull s3p = fadd2(H[1], H[3]);   // wire3 (bit0)

        // <Z_w> = 1 - 2*s_w/nrm
        float n0, n1;
        unpack2(nrm2, n0, n1);
        ull m2inv = pack2(__fdividef(-2.0f, n0), __fdividef(-2.0f, n1));
        ull ones  = pack2(1.0f, 1.0f);

        ull z0 = ffma2(s0p, m2inv, ones);
        ull z1 = ffma2(s1p, m2inv, ones);
        ull z2 = ffma2(s2p, m2inv, ones);
        ull z3 = ffma2(s3p, m2inv, ones);

        float4 o0, o1;
        unpack2(z0, o0.x, o1.x);
        unpack2(z1, o0.y, o1.y);
        unpack2(z2, o0.z, o1.z);
        unpack2(z3, o0.w, o1.w);

        out4[p * 512 + tid]       = o0;   // image 2p
        out4[p * 512 + 256 + tid] = o1;   // image 2p+1
    }
}

extern "C" void kernel_launch(void* const* d_in, const int* in_sizes, int n_in,
                              void* d_out, int out_size)
{
    const float* x = (const float*)d_in[0];
    const float* w = (const float*)d_in[1];
    if (n_in >= 2 && in_sizes[0] == 8) {   // defensive input-order resolution
        x = (const float*)d_in[1];
        w = (const float*)d_in[0];
    }
    quan2d_kernel<<<GRIDSZ, 256>>>((const float4*)x, w, (float4*)d_out);
}

// round 15
// speedup vs baseline: 1.0890x; 1.0890x over previous
#include <cuda_runtime.h>
#include <cuda_bf16.h>

using ull = unsigned long long;

// ---- packed f32x2 helpers (sm_100+ PTX; ptxas never auto-fuses these) ----
__device__ __forceinline__ ull pack2(float lo, float hi) {
    ull r;
    asm("mov.b64 %0, {%1, %2};" : "=l"(r)
        : "r"(__float_as_uint(lo)), "r"(__float_as_uint(hi)));
    return r;
}
__device__ __forceinline__ void unpack2(ull v, float& lo, float& hi) {
    unsigned a, b;
    asm("mov.b64 {%0, %1}, %2;" : "=r"(a), "=r"(b) : "l"(v));
    lo = __uint_as_float(a); hi = __uint_as_float(b);
}
__device__ __forceinline__ ull ffma2(ull a, ull b, ull c) {
    ull d; asm("fma.rn.f32x2 %0, %1, %2, %3;" : "=l"(d) : "l"(a), "l"(b), "l"(c));
    return d;
}
__device__ __forceinline__ ull fmul2(ull a, ull b) {
    ull d; asm("mul.rn.f32x2 %0, %1, %2;" : "=l"(d) : "l"(a), "l"(b));
    return d;
}
__device__ __forceinline__ ull fadd2(ull a, ull b) {
    ull d; asm("add.rn.f32x2 %0, %1, %2;" : "=l"(d) : "l"(a), "l"(b));
    return d;
}

// Warp-private slab: 6 image rows, interleaved {img0,img1} per pixel,
// 36 float2 per row (34 used + 2 pad). NO block-wide barrier anywhere.
__global__ __launch_bounds__(256, 5)
void quan2d_kernel(const float4* __restrict__ x4,
                   const float* __restrict__ w,
                   float4* __restrict__ out4)
{
    __shared__ float2 slab[8][6 * 36];
    __shared__ ull    wc[8][16];   // per-warp constants: [0..7]={r,r}, [8..15]={-r,-r}

    const int tid  = threadIdx.x;
    const int k    = tid >> 5;        // warp id: handles patch rows 2k, 2k+1
    const int lane = tid & 31;
    const int img0 = blockIdx.x * 2;

    // Per-warp gate constants (r = tan(theta/2); cosine factors cancel in <Z>)
    if (lane < 8) {
        float sv, cv;
        sincosf(w[lane] * 0.5f, &sv, &cv);
        float r = __fdividef(sv, cv);
        wc[k][lane]     = pack2(r, r);
        wc[k][8 + lane] = pack2(-r, -r);
    }

    // Zero right-pad pixels 32..35 of each slab row (12 float4)
    if (lane < 12) {
        int row6 = lane >> 1, off = 32 + (lane & 1) * 2;
        *reinterpret_cast<float4*>(&slab[k][row6 * 36 + off]) =
            make_float4(0.f, 0.f, 0.f, 0.f);
    }

    // Round A: rows 4k..4k+3 (always in-bounds). lane -> x4[img*256 + 32k + lane]:
    // fully coalesced. Interleave two images into the slab (2 STS.128).
    {
        int row6 = lane >> 3, quad = lane & 7;
        const float4* src = x4 + img0 * 256 + (4 * k + row6) * 8 + quad;
        float4 f0 = src[0];
        float4 f1 = src[256];
        float4 lo = make_float4(f0.x, f1.x, f0.y, f1.y);
        float4 hi = make_float4(f0.z, f1.z, f0.w, f1.w);
        float2* dst = &slab[k][row6 * 36 + quad * 4];
        *reinterpret_cast<float4*>(dst)     = lo;
        *reinterpret_cast<float4*>(dst + 2) = hi;
    }
    // Round B: rows 4k+4, 4k+5 (overlap with warp k+1's round A; warp 7 -> zeros)
    if (lane < 16) {
        int row6 = 4 + (lane >> 3), quad = lane & 7;
        int grow = 4 * k + row6;
        float4 lo = make_float4(0.f, 0.f, 0.f, 0.f), hi = lo;
        if (grow < 32) {
            const float4* src = x4 + img0 * 256 + grow * 8 + quad;
            float4 f0 = src[0];
            float4 f1 = src[256];
            lo = make_float4(f0.x, f1.x, f0.y, f1.y);
            hi = make_float4(f0.z, f1.z, f0.w, f1.w);
        }
        float2* dst = &slab[k][row6 * 36 + quad * 4];
        *reinterpret_cast<float4*>(dst)     = lo;
        *reinterpret_cast<float4*>(dst + 2) = hi;
    }

    __syncwarp();   // warp-local ordering only — warps fully decoupled

    // Gather: patch (ph = 2k + phl, pw); slab rows 2*phl..2*phl+3.
    // 8 conflict-free LDS.128, each yielding two packed {img0,img1} amplitudes.
    const int phl = lane >> 4, pw = lane & 15;
    const ulonglong2* p4 = reinterpret_cast<const ulonglong2*>(&slab[k][0]);
    const int b4 = (phl * 2) * 18 + pw;

    ull a[16];
#pragma unroll
    for (int dr = 0; dr < 4; ++dr) {
        ulonglong2 q0 = p4[b4 + dr * 18];       // dc 0,1
        ulonglong2 q1 = p4[b4 + dr * 18 + 1];   // dc 2,3 (pw=15 -> zeroed pad)
        a[dr * 4 + 0] = q0.x;
        a[dr * 4 + 1] = q0.y;
        a[dr * 4 + 2] = q1.x;
        a[dr * 4 + 3] = q1.y;
    }

    // RY (tangent form): new0 = t0 - r*t1 ; new1 = r*t0 + t1   (wire q -> mask 8>>q)
    auto ry = [&](int m, int gi) {
        ull r2  = wc[k][gi];
        ull nr2 = wc[k][8 + gi];
#pragma unroll
        for (int j = 0; j < 16; ++j) {
            if (j & m) continue;
            ull t0 = a[j], t1 = a[j | m];
            a[j]     = ffma2(nr2, t1, t0);
            a[j | m] = ffma2(r2,  t0, t1);
        }
    };
    // CNOT = compile-time register permutation (free)
    auto cnot = [&](int cb, int tb) {
#pragma unroll
        for (int j = 0; j < 16; ++j)
            if ((j & cb) && !(j & tb)) { ull t = a[j]; a[j] = a[j | tb]; a[j | tb] = t; }
    };

    ry(8, 0); ry(4, 1); ry(2, 2); ry(1, 3);
    cnot(8, 4); cnot(4, 2); cnot(2, 1); cnot(1, 8);
    ry(8, 4); ry(4, 5); ry(2, 6); ry(1, 7);

    // Group sums of squares:
    //   G[g] = sum a[j]^2, j with (bit3,bit2) = g ; H[g] = same for (bit1,bit0)
    ull G[4], H[4];
#pragma unroll
    for (int g = 0; g < 4; ++g) {
        ull acc = fmul2(a[g * 4], a[g * 4]);
#pragma unroll
        for (int kk = 1; kk < 4; ++kk) acc = ffma2(a[g * 4 + kk], a[g * 4 + kk], acc);
        G[g] = acc;
        ull acc2 = fmul2(a[g], a[g]);
#pragma unroll
        for (int kk = 1; kk < 4; ++kk) acc2 = ffma2(a[kk * 4 + g], a[kk * 4 + g], acc2);
        H[g] = acc2;
    }
    ull nrm2 = fadd2(fadd2(G[0], G[1]), fadd2(G[2], G[3]));
    ull s0p = fadd2(G[2], G[3]);   // wire0 (bit3)
    ull s1p = fadd2(G[1], G[3]);   // wire1 (bit2)
    ull s2p = fadd2(H[2], H[3]);   // wire2 (bit1)
    ull s3p = fadd2(H[1], H[3]);   // wire3 (bit0)

    // <Z_w> = 1 - 2*s_w/nrm
    float n0, n1;
    unpack2(nrm2, n0, n1);
    ull m2inv = pack2(__fdividef(-2.0f, n0), __fdividef(-2.0f, n1));
    ull ones  = pack2(1.0f, 1.0f);

    ull z0 = ffma2(s0p, m2inv, ones);
    ull z1 = ffma2(s1p, m2inv, ones);
    ull z2 = ffma2(s2p, m2inv, ones);
    ull z3 = ffma2(s3p, m2inv, ones);

    float4 o0, o1;
    unpack2(z0, o0.x, o1.x);
    unpack2(z1, o0.y, o1.y);
    unpack2(z2, o0.z, o1.z);
    unpack2(z3, o0.w, o1.w);

    // patch id = 32k + 16*phl + pw = tid -> coalesced float4 stores
    out4[img0 * 256 + tid]       = o0;
    out4[(img0 + 1) * 256 + tid] = o1;
}

extern "C" void kernel_launch(void* const* d_in, const int* in_sizes, int n_in,
                              void* d_out, int out_size)
{
    const float* x = (const float*)d_in[0];
    const float* w = (const float*)d_in[1];
    if (n_in >= 2 && in_sizes[0] == 8) {   // defensive input-order resolution
        x = (const float*)d_in[1];
        w = (const float*)d_in[0];
    }
    quan2d_kernel<<<4096, 256>>>((const float4*)x, w, (float4*)d_out);
}